// round 5
// baseline (speedup 1.0000x reference)
#include <cuda_runtime.h>
#include <cstdint>

#define Bsz  128
#define Ssz  512
#define Hsz  512

#define NBLK 128     // 1 CTA per SM, all co-resident
#define NTHR 512     // 16 warps -> 4 per SMSP
#define KS   128     // k-range per warp-quad (4 splits x 128 = 512)

typedef unsigned long long ull;

// Persistent device state (no allocations allowed)
__device__ float    g_Hbuf[2][Hsz][Bsz];   // double-buffered H, [hidden][batch]
__device__ float    g_xT[Ssz][Bsz];        // x transposed to [t][b]
__device__ unsigned g_bar;                 // monotonic grid-barrier counter

// ---------- packed f32x2 helpers ----------
__device__ __forceinline__ ull pack2(float lo, float hi) {
    ull r; asm("mov.b64 %0, {%1, %2};" : "=l"(r) : "f"(lo), "f"(hi)); return r;
}
__device__ __forceinline__ void unpack2(ull v, float& lo, float& hi) {
    asm("mov.b64 {%0, %1}, %2;" : "=f"(lo), "=f"(hi) : "l"(v));
}
__device__ __forceinline__ void ffma2(ull& d, ull a, ull b) {
    asm("fma.rn.f32x2 %0, %1, %2, %0;" : "+l"(d) : "l"(a), "l"(b));
}
__device__ __forceinline__ void fadd2(ull& d, ull a) {
    asm("add.rn.f32x2 %0, %0, %1;" : "+l"(d) : "l"(a));
}
__device__ __forceinline__ float sigmoidf_(float v) {
    float e = __expf(-v);
    return __fdividef(1.0f, 1.0f + e);
}
__device__ __forceinline__ float tanhf_(float v) {
    float x = fminf(fmaxf(v, -15.0f), 15.0f);
    float t = __expf(2.0f * x);
    return __fdividef(t - 1.0f, t + 1.0f);
}

// ---------- cp.async helpers ----------
__device__ __forceinline__ void cp16(uint32_t dst_smem, const void* src) {
    asm volatile("cp.async.cg.shared.global [%0], [%1], 16;"
                 :: "r"(dst_smem), "l"(src));
}
__device__ __forceinline__ void cp_commit() {
    asm volatile("cp.async.commit_group;");
}
template<int N> __device__ __forceinline__ void cp_wait() {
    asm volatile("cp.async.wait_group %0;" :: "n"(N));
}

// ---------- lightweight grid barrier primitives ----------
__device__ __forceinline__ void bar_arrive_release() {
    asm volatile("red.release.gpu.global.add.u32 [%0], 1;"
                 :: "l"(&g_bar) : "memory");
}
__device__ __forceinline__ void bar_spin_acquire(unsigned target) {
    unsigned v;
    do {
        asm volatile("ld.acquire.gpu.global.u32 %0, [%1];"
                     : "=r"(v) : "l"(&g_bar) : "memory");
    } while (v < target);
}

// ---------- init: reset barrier, transpose H_prev and x ----------
__global__ void lstm_init_kernel(const float* __restrict__ Hprev,
                                 const float* __restrict__ x) {
    int i = blockIdx.x * blockDim.x + threadIdx.x;
    if (i == 0) g_bar = 0;
    if (i < Bsz * Hsz) {                       // H_prev [B][H] -> [h][b]
        int b = i / Hsz, h = i % Hsz;
        g_Hbuf[0][h][b] = Hprev[i];
    }
    if (i < Bsz * Ssz) {                       // x [B][S] -> [t][b]
        int t = i >> 7, b = i & 127;
        g_xT[t][b] = x[b * Ssz + t];
    }
}

// ---------- main persistent kernel ----------
__global__ __launch_bounds__(NTHR, 1)
void lstm_kernel(const float* __restrict__ Cprev,
                 const float* __restrict__ Wi, const float* __restrict__ bi,
                 const float* __restrict__ Wf, const float* __restrict__ bf,
                 const float* __restrict__ Wc, const float* __restrict__ bc,
                 const float* __restrict__ Wo, const float* __restrict__ bo,
                 float* __restrict__ out)
{
    extern __shared__ float smem[];
    float* Ws    = smem;                    // [512][32]  weight slice (64KB)
    float* Hs    = Ws + Hsz * 32;           // 16 x [128k][16b] warp-private (128KB)
    float* parts = Hs + Hsz * 64;           // [3][2048]  k-split partials (24KB)
    float* W0s   = parts + 3 * 2048;        // [32]
    float* Bs    = W0s + 32;                // [32]

    const int tid  = threadIdx.x;
    const int warp = tid >> 5;
    const int lane = tid & 31;
    const int s    = warp >> 2;             // k-split 0..3
    const int w2   = warp & 3;
    const int ty   = lane & 7;              // hidden unit within CTA (0..7)
    const int tx   = (lane >> 3) | (w2 << 2);   // batch tile (0..15)

    const int cta   = blockIdx.x;
    const int b_off = (cta & 1) * 64;
    const int h_off = (cta >> 1) * 8;
    const int b0    = b_off + tx * 4;
    const int h     = h_off + ty;
    const int kbeg  = s * KS;

    // --- one-time weight slice load: Ws[k][gc], gc = ty*4 + gate ---
    const float* Wg[4] = {Wi, Wf, Wc, Wo};
    const float* bg[4] = {bi, bf, bc, bo};
    for (int idx = tid; idx < Hsz * 32; idx += NTHR) {
        int k = idx >> 5, gc = idx & 31;
        int hh = h_off + (gc >> 2), g = gc & 3;
        Ws[idx] = Wg[g][(k + 1) * Hsz + hh];
    }
    if (tid < 32) {
        int hh = h_off + (tid >> 2), g = tid & 3;
        W0s[tid] = Wg[g][hh];
        Bs[tid]  = bg[g][hh];
    }

    // warp-private H staging addresses (each warp stages only what it reads):
    // region = warp*2048 floats, row = k-kbeg (16 floats = its 16 batches)
    float* Hwarp = Hs + warp * 2048;
    uint32_t hs_dst = (uint32_t)__cvta_generic_to_shared(
                          Hwarp + (lane >> 2) * 16 + (lane & 3) * 4);
    const char* hsrc_base = (const char*)
        &g_Hbuf[0][kbeg + (lane >> 2)][b_off + w2 * 16 + (lane & 3) * 4];
    const size_t hbuf_stride = (size_t)Hsz * Bsz * sizeof(float);

    // --- C state in registers (only s==3 threads own it) ---
    float Creg[4], Hn[4];
#pragma unroll
    for (int j = 0; j < 4; ++j) Creg[j] = Cprev[(b0 + j) * Hsz + h];

    __syncthreads();   // weights + W0s/Bs ready (only full-CTA sync in kernel)

    int cur = 0;
    for (int t = 0; t < Ssz; ++t) {
        // prefetch x for the combiner early
        float4 xa;
        if (s == 3) xa = *(const float4*)&g_xT[t][b0];

        // ---- per-warp staging: 4 sub-chunk groups of 32 k-rows (2KB each) ----
        {
            const char* src = hsrc_base + (size_t)cur * hbuf_stride;
#pragma unroll
            for (int c = 0; c < 4; ++c) {
#pragma unroll
                for (int i = 0; i < 4; ++i) {
                    int row = c * 32 + i * 8;
                    cp16(hs_dst + row * 64, src + (size_t)row * Bsz * 4);
                }
                cp_commit();
            }
        }

        // accumulators: combiner (s==3) seeds with bias + x*W_row0; others zero
        ull acc[2][4];
        if (s == 3) {
#pragma unroll
            for (int g = 0; g < 4; ++g) {
                float w0 = W0s[ty * 4 + g], bb = Bs[ty * 4 + g];
                acc[0][g] = pack2(fmaf(xa.x, w0, bb), fmaf(xa.y, w0, bb));
                acc[1][g] = pack2(fmaf(xa.z, w0, bb), fmaf(xa.w, w0, bb));
            }
        } else {
#pragma unroll
            for (int g = 0; g < 4; ++g) { acc[0][g] = 0ull; acc[1][g] = 0ull; }
        }

        // ---- GEMM quarter, pipelined against own staging ----
        const float4* Hs4 = (const float4*)Hwarp + (lane >> 3);   // + kk*4
        const float4* Ws4 = (const float4*)Ws + kbeg * 8 + ty;    // + kk*8
#pragma unroll
        for (int c = 0; c < 4; ++c) {
            if (c == 0) cp_wait<3>();
            else if (c == 1) cp_wait<2>();
            else if (c == 2) cp_wait<1>();
            else cp_wait<0>();
            __syncwarp();
#pragma unroll 8
            for (int kk2 = 0; kk2 < 32; ++kk2) {
                int kk = c * 32 + kk2;
                float4 h4 = Hs4[kk * 4];
                float4 w4 = Ws4[kk * 8];
                ull h01 = pack2(h4.x, h4.y);
                ull h23 = pack2(h4.z, h4.w);
                ull wd;
                wd = pack2(w4.x, w4.x); ffma2(acc[0][0], h01, wd); ffma2(acc[1][0], h23, wd);
                wd = pack2(w4.y, w4.y); ffma2(acc[0][1], h01, wd); ffma2(acc[1][1], h23, wd);
                wd = pack2(w4.z, w4.z); ffma2(acc[0][2], h01, wd); ffma2(acc[1][2], h23, wd);
                wd = pack2(w4.w, w4.w); ffma2(acc[0][3], h01, wd); ffma2(acc[1][3], h23, wd);
            }
        }

        // k-split partials -> smem (splits 0..2)
        if (s < 3) {
#pragma unroll
            for (int g = 0; g < 4; ++g) {
#pragma unroll
                for (int i = 0; i < 2; ++i)
                    *(ull*)&parts[s * 2048 + (ty * 4 + g) * 64 + tx * 4 + i * 2] = acc[i][g];
            }
        }
        // sync only the 4 warps of this w2 group (named barrier, 128 threads)
        asm volatile("bar.sync %0, 128;" :: "r"(1 + w2) : "memory");

        if (s == 3) {
            // combine partials
#pragma unroll
            for (int g = 0; g < 4; ++g) {
#pragma unroll
                for (int i = 0; i < 2; ++i) {
#pragma unroll
                    for (int ss = 0; ss < 3; ++ss)
                        fadd2(acc[i][g],
                              *(const ull*)&parts[ss * 2048 + (ty * 4 + g) * 64 + tx * 4 + i * 2]);
                }
            }
            // gate order: g0=i, g1=f, g2=c, g3=o
            float ip[4], fp[4], cp[4], op[4];
            unpack2(acc[0][0], ip[0], ip[1]); unpack2(acc[1][0], ip[2], ip[3]);
            unpack2(acc[0][1], fp[0], fp[1]); unpack2(acc[1][1], fp[2], fp[3]);
            unpack2(acc[0][2], cp[0], cp[1]); unpack2(acc[1][2], cp[2], cp[3]);
            unpack2(acc[0][3], op[0], op[1]); unpack2(acc[1][3], op[2], op[3]);
#pragma unroll
            for (int j = 0; j < 4; ++j) {
                float I  = sigmoidf_(ip[j]);
                float F  = sigmoidf_(fp[j]);
                float Ch = tanhf_(cp[j]);
                float Cn = F * Creg[j] + I * Ch;
                Creg[j]  = Cn;
                Hn[j]    = op[j] * tanhf_(Cn);   // O has no sigmoid (faithful)
            }
            *(float4*)&g_Hbuf[cur ^ 1][h][b0] = make_float4(Hn[0], Hn[1], Hn[2], Hn[3]);
            // release-arrive: one per s==3 warp (4 per CTA)
            if (lane == 0) bar_arrive_release();
        }

        // everyone waits for all 4*NBLK arrivals of this step (except last step)
        if (t + 1 < Ssz) {
            if (lane == 0) bar_spin_acquire((unsigned)(t + 1) * (4 * NBLK));
            __syncwarp();
        }
        cur ^= 1;
    }

    // outputs: (H, H, C), each [B][HID]
    if (s == 3) {
#pragma unroll
        for (int j = 0; j < 4; ++j) {
            int base = (b0 + j) * Hsz + h;
            out[base]                 = Hn[j];
            out[Bsz * Hsz + base]     = Hn[j];
            out[2 * Bsz * Hsz + base] = Creg[j];
        }
    }
}

extern "C" void kernel_launch(void* const* d_in, const int* in_sizes, int n_in,
                              void* d_out, int out_size) {
    (void)in_sizes; (void)n_in; (void)out_size;
    const float* x  = (const float*)d_in[0];
    const float* Hp = (const float*)d_in[1];
    const float* Cp = (const float*)d_in[2];
    const float* Wi = (const float*)d_in[3];
    const float* bi = (const float*)d_in[4];
    const float* Wf = (const float*)d_in[5];
    const float* bf = (const float*)d_in[6];
    const float* Wc = (const float*)d_in[7];
    const float* bc = (const float*)d_in[8];
    const float* Wo = (const float*)d_in[9];
    const float* bo = (const float*)d_in[10];

    size_t smem_bytes = (size_t)(Hsz * 32 + Hsz * 64 + 3 * 2048 + 64) * sizeof(float);
    cudaFuncSetAttribute(lstm_kernel,
                         cudaFuncAttributeMaxDynamicSharedMemorySize,
                         (int)smem_bytes);

    lstm_init_kernel<<<(Bsz * Hsz + 255) / 256, 256>>>(Hp, x);
    lstm_kernel<<<NBLK, NTHR, smem_bytes>>>(Cp, Wi, bi, Wf, bf, Wc, bc,
                                            Wo, bo, (float*)d_out);
}

// round 6
// speedup vs baseline: 1.3916x; 1.3916x over previous
#include <cuda_runtime.h>
#include <cstdint>

#define Bsz  128
#define Ssz  512
#define Hsz  512

#define NBLK 128     // 1 CTA per SM, all co-resident
#define NTHR 512     // 16 warps -> 4 per SMSP
#define KS   128     // k-range per warp-quad (4 splits x 128 = 512)

typedef unsigned long long ull;

// Persistent device state (no allocations allowed)
__device__ float    g_Hbuf[2][Hsz][Bsz];   // double-buffered H, [hidden][batch]
__device__ float    g_xT[Ssz][Bsz];        // x transposed to [t][b]
__device__ unsigned g_bar;                 // monotonic grid-barrier counter

// ---------- packed f32x2 helpers ----------
__device__ __forceinline__ ull pack2(float lo, float hi) {
    ull r; asm("mov.b64 %0, {%1, %2};" : "=l"(r) : "f"(lo), "f"(hi)); return r;
}
__device__ __forceinline__ void unpack2(ull v, float& lo, float& hi) {
    asm("mov.b64 {%0, %1}, %2;" : "=f"(lo), "=f"(hi) : "l"(v));
}
__device__ __forceinline__ void ffma2(ull& d, ull a, ull b) {
    asm("fma.rn.f32x2 %0, %1, %2, %0;" : "+l"(d) : "l"(a), "l"(b));
}
__device__ __forceinline__ void fadd2(ull& d, ull a) {
    asm("add.rn.f32x2 %0, %0, %1;" : "+l"(d) : "l"(a));
}
__device__ __forceinline__ float sigmoidf_(float v) {
    float e = __expf(-v);
    return __fdividef(1.0f, 1.0f + e);
}
__device__ __forceinline__ float tanhf_(float v) {
    float x = fminf(fmaxf(v, -15.0f), 15.0f);
    float t = __expf(2.0f * x);
    return __fdividef(t - 1.0f, t + 1.0f);
}

// ---------- cp.async helpers ----------
__device__ __forceinline__ void cp16(uint32_t dst_smem, const void* src) {
    asm volatile("cp.async.cg.shared.global [%0], [%1], 16;"
                 :: "r"(dst_smem), "l"(src));
}
__device__ __forceinline__ void cp_commit() {
    asm volatile("cp.async.commit_group;");
}
template<int N> __device__ __forceinline__ void cp_wait() {
    asm volatile("cp.async.wait_group %0;" :: "n"(N));
}

// ---------- grid barrier: single spinner per CTA (R4 proven) ----------
__device__ __forceinline__ void grid_barrier(unsigned target) {
    __syncthreads();
    if (threadIdx.x == 0) {
        __threadfence();
        atomicAdd(&g_bar, 1u);
        unsigned v;
        do {
            asm volatile("ld.volatile.global.u32 %0, [%1];" : "=r"(v) : "l"(&g_bar));
        } while (v < target);
        __threadfence();
    }
    __syncthreads();
}

// ---------- init: reset barrier, transpose H_prev and x ----------
__global__ void lstm_init_kernel(const float* __restrict__ Hprev,
                                 const float* __restrict__ x) {
    int i = blockIdx.x * blockDim.x + threadIdx.x;
    if (i == 0) g_bar = 0;
    if (i < Bsz * Hsz) {                       // H_prev [B][H] -> [h][b]
        int b = i / Hsz, h = i % Hsz;
        g_Hbuf[0][h][b] = Hprev[i];
    }
    if (i < Bsz * Ssz) {                       // x [B][S] -> [t][b]
        int t = i >> 7, b = i & 127;
        g_xT[t][b] = x[b * Ssz + t];
    }
}

// ---------- main persistent kernel ----------
__global__ __launch_bounds__(NTHR, 1)
void lstm_kernel(const float* __restrict__ Cprev,
                 const float* __restrict__ Wi, const float* __restrict__ bi,
                 const float* __restrict__ Wf, const float* __restrict__ bf,
                 const float* __restrict__ Wc, const float* __restrict__ bc,
                 const float* __restrict__ Wo, const float* __restrict__ bo,
                 float* __restrict__ out)
{
    extern __shared__ float smem[];
    float* Ws    = smem;                    // [512][32]  weight slice (64KB)
    float* Hs    = Ws + Hsz * 32;           // 16 x [128k][16b] warp-private (128KB)
    float* parts = Hs + Hsz * 64;           // [3][2048]  k-split partials (24KB)
    float* W0s   = parts + 3 * 2048;        // [32]
    float* Bs    = W0s + 32;                // [32]

    const int tid  = threadIdx.x;
    const int warp = tid >> 5;
    const int lane = tid & 31;
    const int s    = warp >> 2;             // k-split 0..3
    const int w2   = warp & 3;
    const int ty   = lane & 7;              // hidden unit within CTA (0..7)
    const int tx   = (lane >> 3) | (w2 << 2);   // batch tile (0..15)

    const int cta   = blockIdx.x;
    const int b_off = (cta & 1) * 64;
    const int h_off = (cta >> 1) * 8;
    const int b0    = b_off + tx * 4;
    const int h     = h_off + ty;
    const int kbeg  = s * KS;

    // --- one-time weight slice load: Ws[k][gc], gc = ty*4 + gate ---
    const float* Wg[4] = {Wi, Wf, Wc, Wo};
    const float* bg[4] = {bi, bf, bc, bo};
    for (int idx = tid; idx < Hsz * 32; idx += NTHR) {
        int k = idx >> 5, gc = idx & 31;
        int hh = h_off + (gc >> 2), g = gc & 3;
        Ws[idx] = Wg[g][(k + 1) * Hsz + hh];
    }
    if (tid < 32) {
        int hh = h_off + (tid >> 2), g = tid & 3;
        W0s[tid] = Wg[g][hh];
        Bs[tid]  = bg[g][hh];
    }

    // warp-private H staging: warp stages exactly the 8KB it consumes
    // region = warp*2048 floats; row r (=k-kbeg) holds its 16 batches
    float* Hwarp = Hs + warp * 2048;
    uint32_t hs_dst = (uint32_t)__cvta_generic_to_shared(
                          Hwarp + (lane >> 2) * 16 + (lane & 3) * 4);
    const char* hsrc_base = (const char*)
        &g_Hbuf[0][kbeg + (lane >> 2)][b_off + w2 * 16 + (lane & 3) * 4];
    const size_t hbuf_stride = (size_t)Hsz * Bsz * sizeof(float);

    // --- C state in registers (only s==3 threads own it) ---
    float Creg[4], Hn[4];
#pragma unroll
    for (int j = 0; j < 4; ++j) Creg[j] = Cprev[(b0 + j) * Hsz + h];

    __syncthreads();   // weights + W0s/Bs ready

    int cur = 0;
    for (int t = 0; t < Ssz; ++t) {
        // ---- per-warp staging: 4 chunked groups of 32 k-rows (2KB each) ----
        {
            const char* src = hsrc_base + (size_t)cur * hbuf_stride;
#pragma unroll
            for (int c = 0; c < 4; ++c) {
#pragma unroll
                for (int i = 0; i < 4; ++i) {
                    int row = c * 32 + i * 8;
                    cp16(hs_dst + row * 64, src + (size_t)row * Bsz * 4);
                }
                cp_commit();
            }
        }

        // accumulators: combiner (s==3) seeds with bias + x*W_row0; others zero
        ull acc[2][4];
        if (s == 3) {
            float4 xa = *(const float4*)&g_xT[t][b0];
#pragma unroll
            for (int g = 0; g < 4; ++g) {
                float w0 = W0s[ty * 4 + g], bb = Bs[ty * 4 + g];
                acc[0][g] = pack2(fmaf(xa.x, w0, bb), fmaf(xa.y, w0, bb));
                acc[1][g] = pack2(fmaf(xa.z, w0, bb), fmaf(xa.w, w0, bb));
            }
        } else {
#pragma unroll
            for (int g = 0; g < 4; ++g) { acc[0][g] = 0ull; acc[1][g] = 0ull; }
        }

        // ---- GEMM quarter, chunks pipelined against own staging ----
        const float4* Hs4 = (const float4*)Hwarp + (lane >> 3);   // + kk*4
        const float4* Ws4 = (const float4*)Ws + kbeg * 8 + ty;    // + kk*8
#pragma unroll
        for (int c = 0; c < 4; ++c) {
            if      (c == 0) cp_wait<3>();
            else if (c == 1) cp_wait<2>();
            else if (c == 2) cp_wait<1>();
            else             cp_wait<0>();
            __syncwarp();
#pragma unroll 8
            for (int kk2 = 0; kk2 < 32; ++kk2) {
                int kk = c * 32 + kk2;
                float4 h4 = Hs4[kk * 4];
                float4 w4 = Ws4[kk * 8];
                ull h01 = pack2(h4.x, h4.y);
                ull h23 = pack2(h4.z, h4.w);
                ull wd;
                wd = pack2(w4.x, w4.x); ffma2(acc[0][0], h01, wd); ffma2(acc[1][0], h23, wd);
                wd = pack2(w4.y, w4.y); ffma2(acc[0][1], h01, wd); ffma2(acc[1][1], h23, wd);
                wd = pack2(w4.z, w4.z); ffma2(acc[0][2], h01, wd); ffma2(acc[1][2], h23, wd);
                wd = pack2(w4.w, w4.w); ffma2(acc[0][3], h01, wd); ffma2(acc[1][3], h23, wd);
            }
        }

        // k-split partials -> smem (splits 0..2), sync the 4-warp w2 group
        if (s < 3) {
#pragma unroll
            for (int g = 0; g < 4; ++g) {
#pragma unroll
                for (int i = 0; i < 2; ++i)
                    *(ull*)&parts[s * 2048 + (ty * 4 + g) * 64 + tx * 4 + i * 2] = acc[i][g];
            }
        }
        asm volatile("bar.sync %0, 128;" :: "r"(1 + w2) : "memory");

        if (s == 3) {
            // combine partials
#pragma unroll
            for (int g = 0; g < 4; ++g) {
#pragma unroll
                for (int i = 0; i < 2; ++i) {
#pragma unroll
                    for (int ss = 0; ss < 3; ++ss)
                        fadd2(acc[i][g],
                              *(const ull*)&parts[ss * 2048 + (ty * 4 + g) * 64 + tx * 4 + i * 2]);
                }
            }
            // gate order: g0=i, g1=f, g2=c, g3=o
            float ip[4], fp[4], cp[4], op[4];
            unpack2(acc[0][0], ip[0], ip[1]); unpack2(acc[1][0], ip[2], ip[3]);
            unpack2(acc[0][1], fp[0], fp[1]); unpack2(acc[1][1], fp[2], fp[3]);
            unpack2(acc[0][2], cp[0], cp[1]); unpack2(acc[1][2], cp[2], cp[3]);
            unpack2(acc[0][3], op[0], op[1]); unpack2(acc[1][3], op[2], op[3]);
#pragma unroll
            for (int j = 0; j < 4; ++j) {
                float I  = sigmoidf_(ip[j]);
                float F  = sigmoidf_(fp[j]);
                float Ch = tanhf_(cp[j]);
                float Cn = F * Creg[j] + I * Ch;
                Creg[j]  = Cn;
                Hn[j]    = op[j] * tanhf_(Cn);   // O has no sigmoid (faithful)
            }
            *(float4*)&g_Hbuf[cur ^ 1][h][b0] = make_float4(Hn[0], Hn[1], Hn[2], Hn[3]);
        }

        grid_barrier((unsigned)(t + 1) * NBLK);
        cur ^= 1;
    }

    // outputs: (H, H, C), each [B][HID]
    if (s == 3) {
#pragma unroll
        for (int j = 0; j < 4; ++j) {
            int base = (b0 + j) * Hsz + h;
            out[base]                 = Hn[j];
            out[Bsz * Hsz + base]     = Hn[j];
            out[2 * Bsz * Hsz + base] = Creg[j];
        }
    }
}

extern "C" void kernel_launch(void* const* d_in, const int* in_sizes, int n_in,
                              void* d_out, int out_size) {
    (void)in_sizes; (void)n_in; (void)out_size;
    const float* x  = (const float*)d_in[0];
    const float* Hp = (const float*)d_in[1];
    const float* Cp = (const float*)d_in[2];
    const float* Wi = (const float*)d_in[3];
    const float* bi = (const float*)d_in[4];
    const float* Wf = (const float*)d_in[5];
    const float* bf = (const float*)d_in[6];
    const float* Wc = (const float*)d_in[7];
    const float* bc = (const float*)d_in[8];
    const float* Wo = (const float*)d_in[9];
    const float* bo = (const float*)d_in[10];

    size_t smem_bytes = (size_t)(Hsz * 32 + Hsz * 64 + 3 * 2048 + 64) * sizeof(float);
    cudaFuncSetAttribute(lstm_kernel,
                         cudaFuncAttributeMaxDynamicSharedMemorySize,
                         (int)smem_bytes);

    lstm_init_kernel<<<(Bsz * Hsz + 255) / 256, 256>>>(Hp, x);
    lstm_kernel<<<NBLK, NTHR, smem_bytes>>>(Cp, Wi, bi, Wf, bf, Wc, bc,
                                            Wo, bo, (float*)d_out);
}

// round 7
// speedup vs baseline: 1.4362x; 1.0321x over previous
#include <cuda_runtime.h>
#include <cstdint>

#define Bsz  128
#define Ssz  512
#define Hsz  512

#define NBLK 128     // 1 CTA per SM, all co-resident
#define NTHR 512     // 16 warps -> 4 per SMSP
#define KS   128     // k-range per warp-quad (4 splits x 128 = 512)

typedef unsigned long long ull;

// Persistent device state (no allocations allowed)
__device__ float    g_Hbuf[2][Hsz][Bsz];   // double-buffered H, [hidden][batch]
__device__ float    g_xT[Ssz][Bsz];        // x transposed to [t][b]
__device__ unsigned g_bar;                 // monotonic grid-barrier counter

// ---------- packed f32x2 helpers ----------
__device__ __forceinline__ ull pack2(float lo, float hi) {
    ull r; asm("mov.b64 %0, {%1, %2};" : "=l"(r) : "f"(lo), "f"(hi)); return r;
}
__device__ __forceinline__ void unpack2(ull v, float& lo, float& hi) {
    asm("mov.b64 {%0, %1}, %2;" : "=f"(lo), "=f"(hi) : "l"(v));
}
__device__ __forceinline__ void ffma2(ull& d, ull a, ull b) {
    asm("fma.rn.f32x2 %0, %1, %2, %0;" : "+l"(d) : "l"(a), "l"(b));
}
__device__ __forceinline__ void fadd2(ull& d, ull a) {
    asm("add.rn.f32x2 %0, %0, %1;" : "+l"(d) : "l"(a));
}
__device__ __forceinline__ float sigmoidf_(float v) {
    float e = __expf(-v);
    return __fdividef(1.0f, 1.0f + e);
}
__device__ __forceinline__ float tanhf_(float v) {
    float x = fminf(fmaxf(v, -15.0f), 15.0f);
    float t = __expf(2.0f * x);
    return __fdividef(t - 1.0f, t + 1.0f);
}

// ---------- cp.async helpers ----------
__device__ __forceinline__ void cp16(uint32_t dst_smem, const void* src) {
    asm volatile("cp.async.cg.shared.global [%0], [%1], 16;"
                 :: "r"(dst_smem), "l"(src));
}
__device__ __forceinline__ void cp_commit() {
    asm volatile("cp.async.commit_group;");
}
template<int N> __device__ __forceinline__ void cp_wait() {
    asm volatile("cp.async.wait_group %0;" :: "n"(N));
}

// ---------- grid barrier: release-arrive / acquire-spin, no MEMBAR ----------
__device__ __forceinline__ void grid_barrier(unsigned target) {
    __syncthreads();                    // all CTA work (reads+writes) done
    if (threadIdx.x == 0) {
        asm volatile("red.release.gpu.global.add.u32 [%0], 1;"
                     :: "l"(&g_bar) : "memory");
        unsigned v;
        do {
            asm volatile("ld.acquire.gpu.global.u32 %0, [%1];"
                         : "=r"(v) : "l"(&g_bar) : "memory");
        } while (v < target);
    }
    __syncthreads();                    // broadcast release
}

// ---------- init: reset barrier, transpose H_prev and x ----------
__global__ void lstm_init_kernel(const float* __restrict__ Hprev,
                                 const float* __restrict__ x) {
    int i = blockIdx.x * blockDim.x + threadIdx.x;
    if (i == 0) g_bar = 0;
    if (i < Bsz * Hsz) {                       // H_prev [B][H] -> [h][b]
        int b = i / Hsz, h = i % Hsz;
        g_Hbuf[0][h][b] = Hprev[i];
    }
    if (i < Bsz * Ssz) {                       // x [B][S] -> [t][b]
        int t = i >> 7, b = i & 127;
        g_xT[t][b] = x[b * Ssz + t];
    }
}

// ---------- main persistent kernel ----------
__global__ __launch_bounds__(NTHR, 1)
void lstm_kernel(const float* __restrict__ Cprev,
                 const float* __restrict__ Wi, const float* __restrict__ bi,
                 const float* __restrict__ Wf, const float* __restrict__ bf,
                 const float* __restrict__ Wc, const float* __restrict__ bc,
                 const float* __restrict__ Wo, const float* __restrict__ bo,
                 float* __restrict__ out)
{
    extern __shared__ float smem[];
    float* Ws    = smem;                    // [512][32]  weight slice (64KB)
    float* Hs    = Ws + Hsz * 32;           // 16 x [128k][16b] warp-private (128KB)
    float* parts = Hs + Hsz * 64;           // [3][2048]  k-split partials (24KB)
    float* W0s   = parts + 3 * 2048;        // [32]
    float* Bs    = W0s + 32;                // [32]

    const int tid  = threadIdx.x;
    const int warp = tid >> 5;
    const int lane = tid & 31;
    const int s    = warp >> 2;             // k-split 0..3
    const int w2   = warp & 3;
    const int ty   = lane & 7;              // hidden unit within CTA (0..7)
    const int tx   = (lane >> 3) | (w2 << 2);   // batch tile (0..15)

    const int cta   = blockIdx.x;
    const int b_off = (cta & 1) * 64;
    const int h_off = (cta >> 1) * 8;
    const int b0    = b_off + tx * 4;
    const int h     = h_off + ty;
    const int kbeg  = s * KS;

    // --- one-time weight slice load: Ws[k][gc], gc = ty*4 + gate ---
    const float* Wg[4] = {Wi, Wf, Wc, Wo};
    const float* bg[4] = {bi, bf, bc, bo};
    for (int idx = tid; idx < Hsz * 32; idx += NTHR) {
        int k = idx >> 5, gc = idx & 31;
        int hh = h_off + (gc >> 2), g = gc & 3;
        Ws[idx] = Wg[g][(k + 1) * Hsz + hh];
    }
    if (tid < 32) {
        int hh = h_off + (tid >> 2), g = tid & 3;
        W0s[tid] = Wg[g][hh];
        Bs[tid]  = bg[g][hh];
    }

    // warp-private H staging: warp stages exactly the 8KB it consumes
    float* Hwarp = Hs + warp * 2048;
    uint32_t hs_dst = (uint32_t)__cvta_generic_to_shared(
                          Hwarp + (lane >> 2) * 16 + (lane & 3) * 4);
    const char* hsrc_base = (const char*)
        &g_Hbuf[0][kbeg + (lane >> 2)][b_off + w2 * 16 + (lane & 3) * 4];
    const size_t hbuf_stride = (size_t)Hsz * Bsz * sizeof(float);

    // --- C state in registers (only s==3 threads own it) ---
    float Creg[4], Hn[4];
#pragma unroll
    for (int j = 0; j < 4; ++j) Creg[j] = Cprev[(b0 + j) * Hsz + h];

    __syncthreads();   // weights + W0s/Bs ready

    int cur = 0;
    for (int t = 0; t < Ssz; ++t) {
        // x load issued before the staging burst (combiners only)
        float4 xa;
        if (s == 3) xa = *(const float4*)&g_xT[t][b0];

        // ---- per-warp staging: 4 chunked groups of 32 k-rows (2KB each) ----
        {
            const char* src = hsrc_base + (size_t)cur * hbuf_stride;
#pragma unroll
            for (int c = 0; c < 4; ++c) {
#pragma unroll
                for (int i = 0; i < 4; ++i) {
                    int row = c * 32 + i * 8;
                    cp16(hs_dst + row * 64, src + (size_t)row * Bsz * 4);
                }
                cp_commit();
            }
        }

        // accumulators: combiner (s==3) seeds with bias + x*W_row0; others zero
        ull acc[2][4];
        if (s == 3) {
#pragma unroll
            for (int g = 0; g < 4; ++g) {
                float w0 = W0s[ty * 4 + g], bb = Bs[ty * 4 + g];
                acc[0][g] = pack2(fmaf(xa.x, w0, bb), fmaf(xa.y, w0, bb));
                acc[1][g] = pack2(fmaf(xa.z, w0, bb), fmaf(xa.w, w0, bb));
            }
        } else {
#pragma unroll
            for (int g = 0; g < 4; ++g) { acc[0][g] = 0ull; acc[1][g] = 0ull; }
        }

        // ---- GEMM quarter, chunks pipelined against own staging ----
        const float4* Hs4 = (const float4*)Hwarp + (lane >> 3);   // + kk*4
        const float4* Ws4 = (const float4*)Ws + kbeg * 8 + ty;    // + kk*8
#pragma unroll
        for (int c = 0; c < 4; ++c) {
            if      (c == 0) cp_wait<3>();
            else if (c == 1) cp_wait<2>();
            else if (c == 2) cp_wait<1>();
            else             cp_wait<0>();
            __syncwarp();
#pragma unroll 8
            for (int kk2 = 0; kk2 < 32; ++kk2) {
                int kk = c * 32 + kk2;
                float4 h4 = Hs4[kk * 4];
                float4 w4 = Ws4[kk * 8];
                ull h01 = pack2(h4.x, h4.y);
                ull h23 = pack2(h4.z, h4.w);
                ull wd;
                wd = pack2(w4.x, w4.x); ffma2(acc[0][0], h01, wd); ffma2(acc[1][0], h23, wd);
                wd = pack2(w4.y, w4.y); ffma2(acc[0][1], h01, wd); ffma2(acc[1][1], h23, wd);
                wd = pack2(w4.z, w4.z); ffma2(acc[0][2], h01, wd); ffma2(acc[1][2], h23, wd);
                wd = pack2(w4.w, w4.w); ffma2(acc[0][3], h01, wd); ffma2(acc[1][3], h23, wd);
            }
        }

        // k-split partials -> smem as float4 (splits 0..2)
        if (s < 3) {
#pragma unroll
            for (int g = 0; g < 4; ++g) {
                float4 p;
                unpack2(acc[0][g], p.x, p.y);
                unpack2(acc[1][g], p.z, p.w);
                *(float4*)&parts[s * 2048 + (ty * 4 + g) * 64 + tx * 4] = p;
            }
        }
        asm volatile("bar.sync %0, 128;" :: "r"(1 + w2) : "memory");

        if (s == 3) {
            // combine partials (float4 loads)
#pragma unroll
            for (int g = 0; g < 4; ++g) {
#pragma unroll
                for (int ss = 0; ss < 3; ++ss) {
                    float4 p = *(const float4*)
                        &parts[ss * 2048 + (ty * 4 + g) * 64 + tx * 4];
                    fadd2(acc[0][g], pack2(p.x, p.y));
                    fadd2(acc[1][g], pack2(p.z, p.w));
                }
            }
            // gate order: g0=i, g1=f, g2=c, g3=o
            float ip[4], fp[4], cp[4], op[4];
            unpack2(acc[0][0], ip[0], ip[1]); unpack2(acc[1][0], ip[2], ip[3]);
            unpack2(acc[0][1], fp[0], fp[1]); unpack2(acc[1][1], fp[2], fp[3]);
            unpack2(acc[0][2], cp[0], cp[1]); unpack2(acc[1][2], cp[2], cp[3]);
            unpack2(acc[0][3], op[0], op[1]); unpack2(acc[1][3], op[2], op[3]);
#pragma unroll
            for (int j = 0; j < 4; ++j) {
                float I  = sigmoidf_(ip[j]);
                float F  = sigmoidf_(fp[j]);
                float Ch = tanhf_(cp[j]);
                float Cn = F * Creg[j] + I * Ch;
                Creg[j]  = Cn;
                Hn[j]    = op[j] * tanhf_(Cn);   // O has no sigmoid (faithful)
            }
            *(float4*)&g_Hbuf[cur ^ 1][h][b0] = make_float4(Hn[0], Hn[1], Hn[2], Hn[3]);
        }

        grid_barrier((unsigned)(t + 1) * NBLK);
        cur ^= 1;
    }

    // outputs: (H, H, C), each [B][HID]
    if (s == 3) {
#pragma unroll
        for (int j = 0; j < 4; ++j) {
            int base = (b0 + j) * Hsz + h;
            out[base]                 = Hn[j];
            out[Bsz * Hsz + base]     = Hn[j];
            out[2 * Bsz * Hsz + base] = Creg[j];
        }
    }
}

extern "C" void kernel_launch(void* const* d_in, const int* in_sizes, int n_in,
                              void* d_out, int out_size) {
    (void)in_sizes; (void)n_in; (void)out_size;
    const float* x  = (const float*)d_in[0];
    const float* Hp = (const float*)d_in[1];
    const float* Cp = (const float*)d_in[2];
    const float* Wi = (const float*)d_in[3];
    const float* bi = (const float*)d_in[4];
    const float* Wf = (const float*)d_in[5];
    const float* bf = (const float*)d_in[6];
    const float* Wc = (const float*)d_in[7];
    const float* bc = (const float*)d_in[8];
    const float* Wo = (const float*)d_in[9];
    const float* bo = (const float*)d_in[10];

    size_t smem_bytes = (size_t)(Hsz * 32 + Hsz * 64 + 3 * 2048 + 64) * sizeof(float);
    cudaFuncSetAttribute(lstm_kernel,
                         cudaFuncAttributeMaxDynamicSharedMemorySize,
                         (int)smem_bytes);

    lstm_init_kernel<<<(Bsz * Hsz + 255) / 256, 256>>>(Hp, x);
    lstm_kernel<<<NBLK, NTHR, smem_bytes>>>(Cp, Wi, bi, Wf, bf, Wc, bc,
                                            Wo, bo, (float*)d_out);
}